// round 15
// baseline (speedup 1.0000x reference)
#include <cuda_runtime.h>
#include <cuda_bf16.h>

#define IMG_H 256
#define IMG_W 256
#define NB 4
#define NK 4

#define TILE_W 128
#define TILE_H 16
#define SM_W   136         // cols tx0-4 .. tx0+131 (16B-aligned halo)
#define SM_H   18          // TILE_H + 2 bottom halo
#define NVEC   (SM_W / 4)  // 34 float4 spans per row
#define NSPAN  (SM_H * NVEC)   // 612
#define NTHREADS 512
#define NWARPS   16
#define GRID_BLOCKS ((IMG_W / TILE_W) * (IMG_H / TILE_H) * NB)   // 2*16*4 = 128

__device__ float        g_acc[NB][8];
__device__ unsigned int g_ticket;

__device__ __constant__ const int   PDY[10] = { 0, 0, 1, 1, 1, 1, 1, 2, 2, 2 };
__device__ __constant__ const int   PDX[10] = { 1, 2, -2, -1, 0, 1, 2, -1, 0, 1 };
__device__ __constant__ const float PDWc[10] = {
    0.93941306f, 0.77880078f,
    0.73161563f, 0.88249690f, 0.93941306f, 0.88249690f, 0.73161563f,
    0.73161563f, 0.77880078f, 0.73161563f
};

// packed f32x2 helpers (sm_103a FFMA2 path)
typedef unsigned long long u64;

__device__ __forceinline__ u64 pack2(float lo, float hi) {
    u64 r;
    asm("mov.b64 %0, {%1, %2};" : "=l"(r) : "f"(lo), "f"(hi));
    return r;
}
__device__ __forceinline__ void unpack2(u64 v, float& lo, float& hi) {
    asm("mov.b64 {%0, %1}, %2;" : "=f"(lo), "=f"(hi) : "l"(v));
}
__device__ __forceinline__ void fma2acc(u64& d, u64 a, u64 b) {
    asm("fma.rn.f32x2 %0, %1, %2, %3;" : "=l"(d) : "l"(a), "l"(b), "l"(d));
}
__device__ __forceinline__ u64 fma2(u64 a, u64 b, u64 c) {
    u64 r;
    asm("fma.rn.f32x2 %0, %1, %2, %3;" : "=l"(r) : "l"(a), "l"(b), "l"(c));
    return r;
}
__device__ __forceinline__ void add2acc(u64& d, u64 a) {
    asm("add.rn.f32x2 %0, %1, %2;" : "=l"(d) : "l"(a), "l"(d));
}

// enc bank-conflict swizzle: spreads lane-stride-4 granule accesses.
__device__ __forceinline__ int swz(int c) { return c ^ ((c >> 3) & 7); }

__global__ __launch_bounds__(NTHREADS, 1)
void sncl_fused_kernel(const float* __restrict__ image,
                       const float* __restrict__ enc,
                       float* __restrict__ out) {
    const int b   = blockIdx.z;
    const int tx0 = blockIdx.x * TILE_W;
    const int ty0 = blockIdx.y * TILE_H;

    __shared__ float  sgray[SM_H][SM_W];
    __shared__ float4 senc [SM_H][SM_W];   // stored at swizzled column index
    __shared__ float  part [NWARPS][8];

    const int tid = threadIdx.y * 32 + threadIdx.x;   // blockDim = (32,16)
    const float* img0 = image + (size_t)b * 3 * IMG_H * IMG_W;
    const float* e0   = enc   + (size_t)b * 4 * IMG_H * IMG_W;
    const int HW = IMG_H * IMG_W;

    // Halo fill: 18 rows x 34 float4-spans = 612 over 512 threads.
    // OOB span => 0 (zero padding).
    #pragma unroll
    for (int i = tid; i < NSPAN; i += NTHREADS) {
        int r  = i / NVEC;
        int v  = i - r * NVEC;
        int gy = ty0 + r;
        int gx = tx0 - 4 + v * 4;

        float4 i0 = make_float4(0.f,0.f,0.f,0.f), i1 = i0, i2 = i0;
        float4 c0 = i0, c1 = i0, c2 = i0, c3 = i0;
        if (gy < IMG_H && (unsigned)gx < (unsigned)IMG_W) {
            int off = gy * IMG_W + gx;
            i0 = *(const float4*)(img0 + off);
            i1 = *(const float4*)(img0 + HW + off);
            i2 = *(const float4*)(img0 + 2 * HW + off);
            c0 = *(const float4*)(e0 + off);
            c1 = *(const float4*)(e0 + HW + off);
            c2 = *(const float4*)(e0 + 2 * HW + off);
            c3 = *(const float4*)(e0 + 3 * HW + off);
        }
        float4 g4;
        g4.x = (i0.x + i1.x + i2.x) * (1.0f / 3.0f);
        g4.y = (i0.y + i1.y + i2.y) * (1.0f / 3.0f);
        g4.z = (i0.z + i1.z + i2.z) * (1.0f / 3.0f);
        g4.w = (i0.w + i1.w + i2.w) * (1.0f / 3.0f);
        *(float4*)&sgray[r][v * 4] = g4;
        int cbase = v * 4;
        senc[r][swz(cbase + 0)] = make_float4(c0.x, c1.x, c2.x, c3.x);
        senc[r][swz(cbase + 1)] = make_float4(c0.y, c1.y, c2.y, c3.y);
        senc[r][swz(cbase + 2)] = make_float4(c0.z, c1.z, c2.z, c3.z);
        senc[r][swz(cbase + 3)] = make_float4(c0.w, c1.w, c2.w, c3.w);
    }
    __syncthreads();

    // Each thread: 4 adjacent pixels in row y = threadIdx.y.
    const int y   = threadIdx.y;
    const int lc0 = threadIdx.x * 4 + 4;
    const int gx0 = tx0 + threadIdx.x * 4;
    const int gy  = ty0 + y;

    float4 cg4 = *(const float4*)&sgray[y][lc0];
    float  cv[4] = {cg4.x, cg4.y, cg4.z, cg4.w};

    float wsum[4] = {0.f, 0.f, 0.f, 0.f};
    u64 nomlo[4], nomhi[4];
    const u64 Z = pack2(0.f, 0.f);
    #pragma unroll
    for (int i = 0; i < 4; i++) { nomlo[i] = Z; nomhi[i] = Z; }

    u64 eclo[4], echi[4];   // center enc, packed halves

    #define TAPP(i, g, elo_, ehi_, DW) do {                                   \
        float d_ = (g) - cv[i];                                               \
        float w_ = fmaf(d_ * d_, (DW) * -0.01f, (DW));                        \
        wsum[i] += w_;                                                        \
        u64 ww_ = pack2(w_, w_);                                              \
        fma2acc(nomlo[i], ww_, (elo_));                                       \
        fma2acc(nomhi[i], ww_, (ehi_));                                       \
    } while (0)

    // ---- dy = 0, dx in {1,2} ----
    {
        float4 grR = *(const float4*)&sgray[y][lc0 + 4];
        float  gz[8] = {cv[0], cv[1], cv[2], cv[3],
                        grR.x, grR.y, grR.z, grR.w};
        ulonglong2 ez[6];
        #pragma unroll
        for (int j = 0; j < 6; j++)
            ez[j] = *(const ulonglong2*)&senc[y][swz(lc0 + j)];
        #pragma unroll
        for (int i = 0; i < 4; i++) { eclo[i] = ez[i].x; echi[i] = ez[i].y; }
        #pragma unroll
        for (int i = 0; i < 4; i++) {
            TAPP(i, gz[i + 1], ez[i + 1].x, ez[i + 1].y, 0.93941306f);
            TAPP(i, gz[i + 2], ez[i + 2].x, ez[i + 2].y, 0.77880078f);
        }
    }

    // ---- dy = 1, dx in [-2,2] ----
    {
        const float* row = sgray[y + 1];
        float4 a  = *(const float4*)(row + lc0 - 4);
        float4 bb = *(const float4*)(row + lc0);
        float4 cc = *(const float4*)(row + lc0 + 4);
        float g1[12] = {a.x,a.y,a.z,a.w, bb.x,bb.y,bb.z,bb.w,
                        cc.x,cc.y,cc.z,cc.w};
        ulonglong2 E[8];
        #pragma unroll
        for (int j = 0; j < 8; j++)
            E[j] = *(const ulonglong2*)&senc[y + 1][swz(lc0 - 2 + j)];
        const float W1[5] = {0.73161563f, 0.88249690f, 0.93941306f,
                             0.88249690f, 0.73161563f};
        #pragma unroll
        for (int i = 0; i < 4; i++) {
            #pragma unroll
            for (int t = 0; t < 5; t++)
                TAPP(i, g1[2 + i + t], E[i + t].x, E[i + t].y, W1[t]);
        }
    }

    // ---- dy = 2, dx in [-1,1] ----
    {
        const float* row = sgray[y + 2];
        float4 a  = *(const float4*)(row + lc0 - 4);
        float4 bb = *(const float4*)(row + lc0);
        float4 cc = *(const float4*)(row + lc0 + 4);
        float g2[12] = {a.x,a.y,a.z,a.w, bb.x,bb.y,bb.z,bb.w,
                        cc.x,cc.y,cc.z,cc.w};
        ulonglong2 E[6];
        #pragma unroll
        for (int j = 0; j < 6; j++)
            E[j] = *(const ulonglong2*)&senc[y + 2][swz(lc0 - 1 + j)];
        const float W2[3] = {0.73161563f, 0.77880078f, 0.73161563f};
        #pragma unroll
        for (int i = 0; i < 4; i++) {
            #pragma unroll
            for (int t = 0; t < 3; t++)
                TAPP(i, g2[3 + i + t], E[i + t].x, E[i + t].y, W2[t]);
        }
    }
    #undef TAPP

    // ---- per-pixel epilogue (packed) ----
    const u64 TWO2 = pack2(2.0f, 2.0f);
    u64 aN_lo = Z, aN_hi = Z, aD_lo = Z, aD_hi = Z;

    #pragma unroll
    for (int i = 0; i < 4; i++) {
        const int gxi = gx0 + i;
        float add = 1.0f;
        if (gy < 2 || gxi < 2 || gxi > IMG_W - 3) {
            // Negative-direction OOB taps: neighbor gray = 0 => common factor
            // exp(-c^2/100); sum the OOB spatial weights.
            float S = 0.0f;
            #pragma unroll
            for (int p = 0; p < 10; p++) {
                int ny = gy - PDY[p];
                int nx = gxi - PDX[p];
                if (ny < 0 || (unsigned)nx >= (unsigned)IMG_W) S += PDWc[p];
            }
            add = fmaf(S, fmaf(cv[i] * cv[i], -0.01f, 1.0f), 1.0f);
        }
        float wd = wsum[i] + add;
        u64 wwd = pack2(wd, wd);
        // num: ec o (2*nom + ec)
        u64 tlo = fma2(TWO2, nomlo[i], eclo[i]);
        u64 thi = fma2(TWO2, nomhi[i], echi[i]);
        fma2acc(aN_lo, eclo[i], tlo);
        fma2acc(aN_hi, echi[i], thi);
        // den: ec*wd + nom
        fma2acc(aD_lo, eclo[i], wwd);
        fma2acc(aD_hi, echi[i], wwd);
        add2acc(aD_lo, nomlo[i]);
        add2acc(aD_hi, nomhi[i]);
    }

    float acc[8];
    unpack2(aN_lo, acc[0], acc[1]);
    unpack2(aN_hi, acc[2], acc[3]);
    unpack2(aD_lo, acc[4], acc[5]);
    unpack2(aD_hi, acc[6], acc[7]);

    // Warp shuffle reduce (warp == threadIdx.y)
    #pragma unroll
    for (int o = 16; o > 0; o >>= 1) {
        #pragma unroll
        for (int j = 0; j < 8; j++)
            acc[j] += __shfl_down_sync(0xffffffffu, acc[j], o);
    }
    if (threadIdx.x == 0) {
        #pragma unroll
        for (int j = 0; j < 8; j++)
            part[threadIdx.y][j] = acc[j];
    }
    __syncthreads();

    if (tid < 8) {
        float s = 0.0f;
        #pragma unroll
        for (int w = 0; w < NWARPS; w++) s += part[w][tid];
        atomicAdd(&g_acc[b][tid], s);
    }
    __syncthreads();

    // Last-block finalize
    __shared__ bool is_last;
    if (tid == 0) {
        __threadfence();
        unsigned int old = atomicAdd(&g_ticket, 1u);
        is_last = (old == (unsigned int)(GRID_BLOCKS - 1));
    }
    __syncthreads();

    if (is_last && tid == 0) {
        __threadfence();
        float total = 0.0f;
        #pragma unroll
        for (int bb = 0; bb < NB; bb++) {
            float s = 0.0f;
            #pragma unroll
            for (int k = 0; k < NK; k++)
                s += g_acc[bb][k] / (g_acc[bb][4 + k] + 1e-8f);
            total += (float)NK - s;
        }
        out[0] = total * (1.0f / NB);
        #pragma unroll
        for (int j = 0; j < NB * 8; j++) ((float*)g_acc)[j] = 0.0f;
        __threadfence();
        g_ticket = 0u;
    }
}

extern "C" void kernel_launch(void* const* d_in, const int* in_sizes, int n_in,
                              void* d_out, int out_size) {
    const float* image = (const float*)d_in[0];
    const float* enc   = (const float*)d_in[1];
    float* out = (float*)d_out;

    dim3 blk(32, 16, 1);
    dim3 grd(IMG_W / TILE_W, IMG_H / TILE_H, NB);
    sncl_fused_kernel<<<grd, blk>>>(image, enc, out);
}

// round 16
// speedup vs baseline: 1.2107x; 1.2107x over previous
#include <cuda_runtime.h>
#include <cuda_bf16.h>

#define IMG_H 256
#define IMG_W 256
#define NB 4
#define NK 4

#define TILE_W 128
#define TILE_H 16
#define SM_W   136         // cols tx0-4 .. tx0+131 (16B-aligned halo)
#define SM_H   18          // TILE_H + 2 bottom halo
#define NVEC   (SM_W / 4)  // 34 float4 spans per row
#define NSPAN  (SM_H * NVEC)   // 612
#define NTHREADS 256
#define GRID_BLOCKS ((IMG_W / TILE_W) * (IMG_H / TILE_H) * NB)   // 2*16*4 = 128

__device__ float        g_acc[NB][8];
__device__ unsigned int g_ticket;

__device__ __constant__ const int   PDY[10] = { 0, 0, 1, 1, 1, 1, 1, 2, 2, 2 };
__device__ __constant__ const int   PDX[10] = { 1, 2, -2, -1, 0, 1, 2, -1, 0, 1 };
__device__ __constant__ const float PDWc[10] = {
    0.93941306f, 0.77880078f,
    0.73161563f, 0.88249690f, 0.93941306f, 0.88249690f, 0.73161563f,
    0.73161563f, 0.77880078f, 0.73161563f
};

// packed f32x2 helpers (sm_103a FFMA2 path)
typedef unsigned long long u64;

__device__ __forceinline__ u64 pack2(float lo, float hi) {
    u64 r;
    asm("mov.b64 %0, {%1, %2};" : "=l"(r) : "f"(lo), "f"(hi));
    return r;
}
__device__ __forceinline__ void unpack2(u64 v, float& lo, float& hi) {
    asm("mov.b64 {%0, %1}, %2;" : "=f"(lo), "=f"(hi) : "l"(v));
}
__device__ __forceinline__ void fma2acc(u64& d, u64 a, u64 b) {
    asm("fma.rn.f32x2 %0, %1, %2, %3;" : "=l"(d) : "l"(a), "l"(b), "l"(d));
}
__device__ __forceinline__ u64 fma2(u64 a, u64 b, u64 c) {
    u64 r;
    asm("fma.rn.f32x2 %0, %1, %2, %3;" : "=l"(r) : "l"(a), "l"(b), "l"(c));
    return r;
}
__device__ __forceinline__ void add2acc(u64& d, u64 a) {
    asm("add.rn.f32x2 %0, %1, %2;" : "=l"(d) : "l"(a), "l"(d));
}

// enc bank-conflict swizzle: spreads lane-stride-4 granule accesses.
__device__ __forceinline__ int swz(int c) { return c ^ ((c >> 3) & 7); }

__global__ __launch_bounds__(NTHREADS, 2)
void sncl_fused_kernel(const float* __restrict__ image,
                       const float* __restrict__ enc,
                       float* __restrict__ out) {
    const int b   = blockIdx.z;
    const int tx0 = blockIdx.x * TILE_W;
    const int ty0 = blockIdx.y * TILE_H;

    __shared__ float  sgray[SM_H][SM_W];
    __shared__ float4 senc [SM_H][SM_W];   // stored at swizzled column index
    __shared__ float  part [8][8];

    const int tid = threadIdx.y * 32 + threadIdx.x;   // blockDim = (32,8)
    const float* img0 = image + (size_t)b * 3 * IMG_H * IMG_W;
    const float* e0   = enc   + (size_t)b * 4 * IMG_H * IMG_W;
    const int HW = IMG_H * IMG_W;

    // Halo fill: 18 rows x 34 float4-spans = 612 over 256 threads.
    // OOB span => 0 (zero padding).
    #pragma unroll
    for (int i = tid; i < NSPAN; i += NTHREADS) {
        int r  = i / NVEC;
        int v  = i - r * NVEC;
        int gy = ty0 + r;
        int gx = tx0 - 4 + v * 4;

        float4 i0 = make_float4(0.f,0.f,0.f,0.f), i1 = i0, i2 = i0;
        float4 c0 = i0, c1 = i0, c2 = i0, c3 = i0;
        if (gy < IMG_H && (unsigned)gx < (unsigned)IMG_W) {
            int off = gy * IMG_W + gx;
            i0 = *(const float4*)(img0 + off);
            i1 = *(const float4*)(img0 + HW + off);
            i2 = *(const float4*)(img0 + 2 * HW + off);
            c0 = *(const float4*)(e0 + off);
            c1 = *(const float4*)(e0 + HW + off);
            c2 = *(const float4*)(e0 + 2 * HW + off);
            c3 = *(const float4*)(e0 + 3 * HW + off);
        }
        float4 g4;
        g4.x = (i0.x + i1.x + i2.x) * (1.0f / 3.0f);
        g4.y = (i0.y + i1.y + i2.y) * (1.0f / 3.0f);
        g4.z = (i0.z + i1.z + i2.z) * (1.0f / 3.0f);
        g4.w = (i0.w + i1.w + i2.w) * (1.0f / 3.0f);
        *(float4*)&sgray[r][v * 4] = g4;
        int cbase = v * 4;
        senc[r][swz(cbase + 0)] = make_float4(c0.x, c1.x, c2.x, c3.x);
        senc[r][swz(cbase + 1)] = make_float4(c0.y, c1.y, c2.y, c3.y);
        senc[r][swz(cbase + 2)] = make_float4(c0.z, c1.z, c2.z, c3.z);
        senc[r][swz(cbase + 3)] = make_float4(c0.w, c1.w, c2.w, c3.w);
    }
    __syncthreads();

    const int lc0 = threadIdx.x * 4 + 4;
    const int gx0 = tx0 + threadIdx.x * 4;

    const u64 Z    = pack2(0.f, 0.f);
    const u64 TWO2 = pack2(2.0f, 2.0f);
    u64 aN_lo = Z, aN_hi = Z, aD_lo = Z, aD_hi = Z;

    // Two 4-pixel rows per thread: y = threadIdx.y and threadIdx.y + 8.
    #pragma unroll
    for (int q = 0; q < 2; q++) {
        const int y  = threadIdx.y + q * 8;
        const int gy = ty0 + y;

        float4 cg4 = *(const float4*)&sgray[y][lc0];
        float  cv[4] = {cg4.x, cg4.y, cg4.z, cg4.w};

        float wsum[4] = {0.f, 0.f, 0.f, 0.f};
        u64 nomlo[4], nomhi[4];
        #pragma unroll
        for (int i = 0; i < 4; i++) { nomlo[i] = Z; nomhi[i] = Z; }

        u64 eclo[4], echi[4];   // center enc, packed halves

        #define TAPP(i, g, elo_, ehi_, DW) do {                               \
            float d_ = (g) - cv[i];                                           \
            float w_ = fmaf(d_ * d_, (DW) * -0.01f, (DW));                    \
            wsum[i] += w_;                                                    \
            u64 ww_ = pack2(w_, w_);                                          \
            fma2acc(nomlo[i], ww_, (elo_));                                   \
            fma2acc(nomhi[i], ww_, (ehi_));                                   \
        } while (0)

        // ---- dy = 0, dx in {1,2} ----
        {
            float4 grR = *(const float4*)&sgray[y][lc0 + 4];
            float  gz[8] = {cv[0], cv[1], cv[2], cv[3],
                            grR.x, grR.y, grR.z, grR.w};
            ulonglong2 ez[6];
            #pragma unroll
            for (int j = 0; j < 6; j++)
                ez[j] = *(const ulonglong2*)&senc[y][swz(lc0 + j)];
            #pragma unroll
            for (int i = 0; i < 4; i++) { eclo[i] = ez[i].x; echi[i] = ez[i].y; }
            #pragma unroll
            for (int i = 0; i < 4; i++) {
                TAPP(i, gz[i + 1], ez[i + 1].x, ez[i + 1].y, 0.93941306f);
                TAPP(i, gz[i + 2], ez[i + 2].x, ez[i + 2].y, 0.77880078f);
            }
        }

        // ---- dy = 1, dx in [-2,2] ----
        {
            const float* row = sgray[y + 1];
            float4 a  = *(const float4*)(row + lc0 - 4);
            float4 bb = *(const float4*)(row + lc0);
            float4 cc = *(const float4*)(row + lc0 + 4);
            float g1[12] = {a.x,a.y,a.z,a.w, bb.x,bb.y,bb.z,bb.w,
                            cc.x,cc.y,cc.z,cc.w};
            ulonglong2 E[8];
            #pragma unroll
            for (int j = 0; j < 8; j++)
                E[j] = *(const ulonglong2*)&senc[y + 1][swz(lc0 - 2 + j)];
            const float W1[5] = {0.73161563f, 0.88249690f, 0.93941306f,
                                 0.88249690f, 0.73161563f};
            #pragma unroll
            for (int i = 0; i < 4; i++) {
                #pragma unroll
                for (int t = 0; t < 5; t++)
                    TAPP(i, g1[2 + i + t], E[i + t].x, E[i + t].y, W1[t]);
            }
        }

        // ---- dy = 2, dx in [-1,1] ----
        {
            const float* row = sgray[y + 2];
            float4 a  = *(const float4*)(row + lc0 - 4);
            float4 bb = *(const float4*)(row + lc0);
            float4 cc = *(const float4*)(row + lc0 + 4);
            float g2[12] = {a.x,a.y,a.z,a.w, bb.x,bb.y,bb.z,bb.w,
                            cc.x,cc.y,cc.z,cc.w};
            ulonglong2 E[6];
            #pragma unroll
            for (int j = 0; j < 6; j++)
                E[j] = *(const ulonglong2*)&senc[y + 2][swz(lc0 - 1 + j)];
            const float W2[3] = {0.73161563f, 0.77880078f, 0.73161563f};
            #pragma unroll
            for (int i = 0; i < 4; i++) {
                #pragma unroll
                for (int t = 0; t < 3; t++)
                    TAPP(i, g2[3 + i + t], E[i + t].x, E[i + t].y, W2[t]);
            }
        }
        #undef TAPP

        // ---- per-pixel epilogue (packed) ----
        #pragma unroll
        for (int i = 0; i < 4; i++) {
            const int gxi = gx0 + i;
            float add = 1.0f;
            if (gy < 2 || gxi < 2 || gxi > IMG_W - 3) {
                // Negative-direction OOB taps: neighbor gray = 0 => common
                // factor exp(-c^2/100); sum the OOB spatial weights.
                float S = 0.0f;
                #pragma unroll
                for (int p = 0; p < 10; p++) {
                    int ny = gy - PDY[p];
                    int nx = gxi - PDX[p];
                    if (ny < 0 || (unsigned)nx >= (unsigned)IMG_W) S += PDWc[p];
                }
                add = fmaf(S, fmaf(cv[i] * cv[i], -0.01f, 1.0f), 1.0f);
            }
            float wd = wsum[i] + add;
            u64 wwd = pack2(wd, wd);
            // num: ec o (2*nom + ec)
            u64 tlo = fma2(TWO2, nomlo[i], eclo[i]);
            u64 thi = fma2(TWO2, nomhi[i], echi[i]);
            fma2acc(aN_lo, eclo[i], tlo);
            fma2acc(aN_hi, echi[i], thi);
            // den: ec*wd + nom
            fma2acc(aD_lo, eclo[i], wwd);
            fma2acc(aD_hi, echi[i], wwd);
            add2acc(aD_lo, nomlo[i]);
            add2acc(aD_hi, nomhi[i]);
        }
    }

    float acc[8];
    unpack2(aN_lo, acc[0], acc[1]);
    unpack2(aN_hi, acc[2], acc[3]);
    unpack2(aD_lo, acc[4], acc[5]);
    unpack2(aD_hi, acc[6], acc[7]);

    // Warp shuffle reduce (warp == threadIdx.y)
    #pragma unroll
    for (int o = 16; o > 0; o >>= 1) {
        #pragma unroll
        for (int j = 0; j < 8; j++)
            acc[j] += __shfl_down_sync(0xffffffffu, acc[j], o);
    }
    if (threadIdx.x == 0) {
        #pragma unroll
        for (int j = 0; j < 8; j++)
            part[threadIdx.y][j] = acc[j];
    }
    __syncthreads();

    if (tid < 8) {
        float s = 0.0f;
        #pragma unroll
        for (int w = 0; w < 8; w++) s += part[w][tid];
        atomicAdd(&g_acc[b][tid], s);
    }
    __syncthreads();

    // Last-block finalize
    __shared__ bool is_last;
    if (tid == 0) {
        __threadfence();
        unsigned int old = atomicAdd(&g_ticket, 1u);
        is_last = (old == (unsigned int)(GRID_BLOCKS - 1));
    }
    __syncthreads();

    if (is_last && tid == 0) {
        __threadfence();
        float total = 0.0f;
        #pragma unroll
        for (int bb = 0; bb < NB; bb++) {
            float s = 0.0f;
            #pragma unroll
            for (int k = 0; k < NK; k++)
                s += g_acc[bb][k] / (g_acc[bb][4 + k] + 1e-8f);
            total += (float)NK - s;
        }
        out[0] = total * (1.0f / NB);
        #pragma unroll
        for (int j = 0; j < NB * 8; j++) ((float*)g_acc)[j] = 0.0f;
        __threadfence();
        g_ticket = 0u;
    }
}

extern "C" void kernel_launch(void* const* d_in, const int* in_sizes, int n_in,
                              void* d_out, int out_size) {
    const float* image = (const float*)d_in[0];
    const float* enc   = (const float*)d_in[1];
    float* out = (float*)d_out;

    dim3 blk(32, 8, 1);
    dim3 grd(IMG_W / TILE_W, IMG_H / TILE_H, NB);
    sncl_fused_kernel<<<grd, blk>>>(image, enc, out);
}